// round 2
// baseline (speedup 1.0000x reference)
#include <cuda_runtime.h>
#include <math.h>
#include <stdint.h>

#define DDIM  256   // embedding dim
#define PDIM  64    // num centroids
#define MTILE 64    // queries per CTA
#define PITCH 68    // padded row pitch (floats); 68*4=272B, 16B-aligned for LDS.128

struct Smem {
    float Ct[DDIM][PITCH];   // centroids transposed: Ct[k][p]
    float Qt[DDIM][PITCH];   // queries transposed:   Qt[k][m]
    float Craw[PDIM][DDIM];  // centroids row-major:  Craw[p][d]
    float wt[PDIM][PITCH];   // sims, then weights, transposed: wt[p][m]
    float qrs[MTILE];        // 1/||q_m||
    float cis[PDIM];         // 1/||c_p||
    float red[4][MTILE];     // reduction scratch
};

__global__ void __launch_bounds__(256, 1)
centroid_kernel(const float* __restrict__ gq,
                const float* __restrict__ gc,
                const int* __restrict__ gmask,      // bool marshalled as int32
                float* __restrict__ gctx,
                float* __restrict__ gw,
                float* __restrict__ ghard)
{
    extern __shared__ unsigned char smem_raw[];
    Smem& s = *reinterpret_cast<Smem*>(smem_raw);

    const int t  = threadIdx.x;
    const int tx = t & 15;        // p-group / d-group
    const int ty = t >> 4;        // m-group
    const int mbase = blockIdx.x * MTILE;

    // ---- Load centroids: build Craw (row-major) and Ct (k-major transpose) ----
    #pragma unroll
    for (int i = 0; i < 16; ++i) {
        int idx4 = t + i * 256;           // 4096 float4 = 64x256 floats
        int p  = idx4 >> 6;
        int d4 = idx4 & 63;
        float4 v = reinterpret_cast<const float4*>(gc)[idx4];
        *reinterpret_cast<float4*>(&s.Craw[p][d4 * 4]) = v;
        int d = d4 * 4;
        s.Ct[d + 0][p] = v.x;
        s.Ct[d + 1][p] = v.y;
        s.Ct[d + 2][p] = v.z;
        s.Ct[d + 3][p] = v.w;
    }

    // ---- Load this CTA's 64 queries, transposed into Qt[k][m] ----
    const float4* qblk = reinterpret_cast<const float4*>(gq + (size_t)mbase * DDIM);
    #pragma unroll
    for (int i = 0; i < 16; ++i) {
        int idx4 = t + i * 256;
        int m  = idx4 >> 6;
        int d4 = idx4 & 63;
        float4 v = qblk[idx4];
        int d = d4 * 4;
        s.Qt[d + 0][m] = v.x;
        s.Qt[d + 1][m] = v.y;
        s.Qt[d + 2][m] = v.z;
        s.Qt[d + 3][m] = v.w;
    }
    __syncthreads();

    // ---- Query inverse norms ----
    {
        int m = t & 63, qtr = t >> 6;
        float a = 0.f;
        #pragma unroll 8
        for (int k = qtr * 64; k < qtr * 64 + 64; ++k) {
            float v = s.Qt[k][m];
            a = fmaf(v, v, a);
        }
        s.red[qtr][m] = a;
    }
    __syncthreads();
    if (t < MTILE) {
        float qq = s.red[0][t] + s.red[1][t] + s.red[2][t] + s.red[3][t];
        s.qrs[t] = rsqrtf(fmaxf(qq, 1e-24f));   // == 1/max(||q||,1e-12)
    }
    __syncthreads();

    // ---- Centroid inverse norms ----
    {
        int p = t & 63, qtr = t >> 6;
        float a = 0.f;
        #pragma unroll 8
        for (int k = qtr * 64; k < qtr * 64 + 64; ++k) {
            float v = s.Ct[k][p];
            a = fmaf(v, v, a);
        }
        s.red[qtr][p] = a;
    }
    __syncthreads();
    if (t < PDIM) {
        float cc = s.red[0][t] + s.red[1][t] + s.red[2][t] + s.red[3][t];
        s.cis[t] = rsqrtf(fmaxf(cc, 1e-24f));
    }
    __syncthreads();

    // ---- GEMM1: raw dot products, 4m x 4p register tile per thread ----
    const int p0 = tx * 4, m0 = ty * 4;
    float a00=0,a01=0,a02=0,a03=0, a10=0,a11=0,a12=0,a13=0;
    float a20=0,a21=0,a22=0,a23=0, a30=0,a31=0,a32=0,a33=0;
    #pragma unroll 4
    for (int k = 0; k < DDIM; ++k) {
        float4 cv = *reinterpret_cast<const float4*>(&s.Ct[k][p0]);
        float4 qv = *reinterpret_cast<const float4*>(&s.Qt[k][m0]);
        a00 = fmaf(qv.x, cv.x, a00); a01 = fmaf(qv.x, cv.y, a01);
        a02 = fmaf(qv.x, cv.z, a02); a03 = fmaf(qv.x, cv.w, a03);
        a10 = fmaf(qv.y, cv.x, a10); a11 = fmaf(qv.y, cv.y, a11);
        a12 = fmaf(qv.y, cv.z, a12); a13 = fmaf(qv.y, cv.w, a13);
        a20 = fmaf(qv.z, cv.x, a20); a21 = fmaf(qv.z, cv.y, a21);
        a22 = fmaf(qv.z, cv.z, a22); a23 = fmaf(qv.z, cv.w, a23);
        a30 = fmaf(qv.w, cv.x, a30); a31 = fmaf(qv.w, cv.y, a31);
        a32 = fmaf(qv.w, cv.z, a32); a33 = fmaf(qv.w, cv.w, a33);
    }

    // ---- Epilogue: scale to cosine sim, apply mask, write transposed sims ----
    {
        const float c0 = s.cis[p0 + 0], c1 = s.cis[p0 + 1];
        const float c2 = s.cis[p0 + 2], c3 = s.cis[p0 + 3];
        const bool k0 = gmask[p0 + 0] != 0, k1 = gmask[p0 + 1] != 0;
        const bool k2 = gmask[p0 + 2] != 0, k3 = gmask[p0 + 3] != 0;
        float accr[4][4] = {{a00,a01,a02,a03},{a10,a11,a12,a13},
                            {a20,a21,a22,a23},{a30,a31,a32,a33}};
        #pragma unroll
        for (int i = 0; i < 4; ++i) {
            float qr = s.qrs[m0 + i];
            s.wt[p0 + 0][m0 + i] = k0 ? accr[i][0] * qr * c0 : -1e9f;
            s.wt[p0 + 1][m0 + i] = k1 ? accr[i][1] * qr * c1 : -1e9f;
            s.wt[p0 + 2][m0 + i] = k2 ? accr[i][2] * qr * c2 : -1e9f;
            s.wt[p0 + 3][m0 + i] = k3 ? accr[i][3] * qr * c3 : -1e9f;
        }
    }
    __syncthreads();

    // ---- Softmax + argmax: 4 lanes per row (m = t>>2, part = t&3) ----
    {
        const int m = t >> 2, part = t & 3;
        float locv[16];
        float mx = -INFINITY;
        int   mi = PDIM;  // sentinel larger than any index
        #pragma unroll
        for (int i = 0; i < 16; ++i) {
            int p = part * 16 + i;
            float v = s.wt[p][m];
            locv[i] = v;
            if (v > mx) { mx = v; mi = p; }   // strict > keeps first occurrence
        }
        #pragma unroll
        for (int off = 1; off < 4; off <<= 1) {
            float omx = __shfl_xor_sync(0xffffffffu, mx, off);
            int   omi = __shfl_xor_sync(0xffffffffu, mi, off);
            if (omx > mx || (omx == mx && omi < mi)) { mx = omx; mi = omi; }
        }
        float ssum = 0.f;
        #pragma unroll
        for (int i = 0; i < 16; ++i) {
            float e = expf(locv[i] - mx);
            locv[i] = e;
            ssum += e;
        }
        #pragma unroll
        for (int off = 1; off < 4; off <<= 1)
            ssum += __shfl_xor_sync(0xffffffffu, ssum, off);
        const float inv = 1.0f / ssum;

        // write weights: shared (for GEMM2) + global
        float4* gwrow = reinterpret_cast<float4*>(gw + (size_t)(mbase + m) * PDIM + part * 16);
        #pragma unroll
        for (int j = 0; j < 4; ++j) {
            float w0 = locv[4 * j + 0] * inv;
            float w1 = locv[4 * j + 1] * inv;
            float w2 = locv[4 * j + 2] * inv;
            float w3 = locv[4 * j + 3] * inv;
            int p = part * 16 + 4 * j;
            s.wt[p + 0][m] = w0;
            s.wt[p + 1][m] = w1;
            s.wt[p + 2][m] = w2;
            s.wt[p + 3][m] = w3;
            gwrow[j] = make_float4(w0, w1, w2, w3);
        }
        if (part == 0) ghard[mbase + m] = (float)mi;
    }
    __syncthreads();

    // ---- GEMM2: context[m][d] = sum_p w[m][p] * C[p][d] (raw centroids) ----
    #pragma unroll
    for (int db = 0; db < 4; ++db) {
        const int d0 = db * 64 + tx * 4;
        float b00=0,b01=0,b02=0,b03=0, b10=0,b11=0,b12=0,b13=0;
        float b20=0,b21=0,b22=0,b23=0, b30=0,b31=0,b32=0,b33=0;
        #pragma unroll 4
        for (int p = 0; p < PDIM; ++p) {
            float4 wv = *reinterpret_cast<const float4*>(&s.wt[p][m0]);
            float4 cv = *reinterpret_cast<const float4*>(&s.Craw[p][d0]);
            b00 = fmaf(wv.x, cv.x, b00); b01 = fmaf(wv.x, cv.y, b01);
            b02 = fmaf(wv.x, cv.z, b02); b03 = fmaf(wv.x, cv.w, b03);
            b10 = fmaf(wv.y, cv.x, b10); b11 = fmaf(wv.y, cv.y, b11);
            b12 = fmaf(wv.y, cv.z, b12); b13 = fmaf(wv.y, cv.w, b13);
            b20 = fmaf(wv.z, cv.x, b20); b21 = fmaf(wv.z, cv.y, b21);
            b22 = fmaf(wv.z, cv.z, b22); b23 = fmaf(wv.z, cv.w, b23);
            b30 = fmaf(wv.w, cv.x, b30); b31 = fmaf(wv.w, cv.y, b31);
            b32 = fmaf(wv.w, cv.z, b32); b33 = fmaf(wv.w, cv.w, b33);
        }
        float* crow0 = gctx + (size_t)(mbase + m0) * DDIM + d0;
        *reinterpret_cast<float4*>(crow0 + 0 * DDIM) = make_float4(b00, b01, b02, b03);
        *reinterpret_cast<float4*>(crow0 + 1 * DDIM) = make_float4(b10, b11, b12, b13);
        *reinterpret_cast<float4*>(crow0 + 2 * DDIM) = make_float4(b20, b21, b22, b23);
        *reinterpret_cast<float4*>(crow0 + 3 * DDIM) = make_float4(b30, b31, b32, b33);
    }
}

extern "C" void kernel_launch(void* const* d_in, const int* in_sizes, int n_in,
                              void* d_out, int out_size)
{
    const float* q = (const float*)d_in[0];
    const float* c = (const float*)d_in[1];
    const int*   mask = (const int*)d_in[2];

    const int Pn = in_sizes[2];              // 64
    const int Dn = in_sizes[1] / Pn;         // 256
    const int B  = in_sizes[0] / Dn;         // 131072

    float* out  = (float*)d_out;
    float* ctx  = out;                           // [B, D]
    float* w    = out + (size_t)B * Dn;          // [B, P]
    float* hard = w   + (size_t)B * Pn;          // [B]

    const size_t shmem = sizeof(Smem);
    cudaFuncSetAttribute(centroid_kernel,
                         cudaFuncAttributeMaxDynamicSharedMemorySize, (int)shmem);
    centroid_kernel<<<B / MTILE, 256, shmem>>>(q, c, mask, ctx, w, hard);
}

// round 3
// speedup vs baseline: 1.3220x; 1.3220x over previous
#include <cuda_runtime.h>
#include <math.h>
#include <stdint.h>

#define DDIM 256
#define PDIM 64
#define MTILE 128
#define NTHREADS 512
#define QPITCH 132   // pitch for Qt/wt rows (floats); %4==0 for LDS.128, stride%32=16 -> 2-way max
#define CPITCH 68    // pitch for Ct rows

typedef unsigned long long ull;

__device__ __forceinline__ void ffma2(ull& acc, ull a, ull b) {
    asm("fma.rn.f32x2 %0, %1, %2, %0;" : "+l"(acc) : "l"(a), "l"(b));
}
__device__ __forceinline__ ull pack2dup(float v) {
    ull r;
    asm("mov.b64 %0, {%1, %1};" : "=l"(r) : "f"(v));
    return r;
}
__device__ __forceinline__ float2 unpack2(ull v) {
    float2 r;
    asm("mov.b64 {%0, %1}, %2;" : "=f"(r.x), "=f"(r.y) : "l"(v));
    return r;
}

// shared memory layout (floats):
//   ct   [256*68]  = 17408   (phase B: first 64*256=16384 floats reused as Craw row-major)
//   qt   [256*132] = 33792   (rows 0..63 reused as wt[64][132] after GEMM1)
//   red  [4*128]   = 512
//   redc [4*64]    = 256
//   qrs  [128]
//   cis  [64]
// total 52160 floats = 208640 B  (< 232448 max dyn smem)
#define OFF_CT   0
#define OFF_QT   (OFF_CT + 256 * CPITCH)
#define OFF_RED  (OFF_QT + 256 * QPITCH)
#define OFF_REDC (OFF_RED + 4 * 128)
#define OFF_QRS  (OFF_REDC + 4 * 64)
#define OFF_CIS  (OFF_QRS + 128)
#define SMEM_FLOATS (OFF_CIS + 64)

__global__ void __launch_bounds__(NTHREADS, 1)
centroid_kernel(const float* __restrict__ gq,
                const float* __restrict__ gc,
                const int* __restrict__ gmask,
                float* __restrict__ gctx,
                float* __restrict__ gw,
                float* __restrict__ ghard)
{
    extern __shared__ float sm[];
    float* ct   = sm + OFF_CT;
    float* qt   = sm + OFF_QT;
    float* wt   = sm + OFF_QT;      // alias: qt rows 0..63 (valid after GEMM1 + sync)
    float* craw = sm + OFF_CT;      // alias: ct region (valid after GEMM1 + sync)
    float* red  = sm + OFF_RED;
    float* redc = sm + OFF_REDC;
    float* qrs  = sm + OFF_QRS;
    float* cis  = sm + OFF_CIS;

    const int t  = threadIdx.x;
    const int tx = t & 15;
    const int ty = t >> 4;          // 0..31
    const int mbase = blockIdx.x * MTILE;
    const int p0 = tx * 4;
    const int m0 = ty * 4;

    // ---- Load centroids transposed: Ct[k][p], pitch 68 ----
    const float4* gc4 = reinterpret_cast<const float4*>(gc);
    #pragma unroll
    for (int i = 0; i < 8; ++i) {
        int idx4 = t + i * NTHREADS;      // 4096 float4
        int p  = idx4 >> 6;
        int d4 = idx4 & 63;
        float4 v = gc4[idx4];
        int d = d4 * 4;
        ct[(d + 0) * CPITCH + p] = v.x;
        ct[(d + 1) * CPITCH + p] = v.y;
        ct[(d + 2) * CPITCH + p] = v.z;
        ct[(d + 3) * CPITCH + p] = v.w;
    }

    // ---- Load 128 queries transposed: Qt[k][m], pitch 132 ----
    const float4* gq4 = reinterpret_cast<const float4*>(gq + (size_t)mbase * DDIM);
    #pragma unroll
    for (int i = 0; i < 16; ++i) {
        int idx4 = t + i * NTHREADS;      // 8192 float4
        int m  = idx4 >> 6;
        int d4 = idx4 & 63;
        float4 v = gq4[idx4];
        int d = d4 * 4;
        qt[(d + 0) * QPITCH + m] = v.x;
        qt[(d + 1) * QPITCH + m] = v.y;
        qt[(d + 2) * QPITCH + m] = v.z;
        qt[(d + 3) * QPITCH + m] = v.w;
    }
    __syncthreads();

    // ---- Partial sum-squares: queries (all 512 threads) and centroids (first 256) ----
    {
        int m = t & 127, qtr = t >> 7;
        float a = 0.f;
        #pragma unroll 8
        for (int k = qtr * 64; k < qtr * 64 + 64; ++k) {
            float v = qt[k * QPITCH + m];
            a = fmaf(v, v, a);
        }
        red[qtr * 128 + m] = a;
    }
    if (t < 256) {
        int p = t & 63, qtr = t >> 6;
        float a = 0.f;
        #pragma unroll 8
        for (int k = qtr * 64; k < qtr * 64 + 64; ++k) {
            float v = ct[k * CPITCH + p];
            a = fmaf(v, v, a);
        }
        redc[qtr * 64 + p] = a;
    }
    __syncthreads();
    if (t < 128) {
        float qq = red[t] + red[128 + t] + red[256 + t] + red[384 + t];
        qrs[t] = rsqrtf(fmaxf(qq, 1e-24f));
    }
    if (t < 64) {
        float cc = redc[t] + redc[64 + t] + redc[128 + t] + redc[192 + t];
        cis[t] = rsqrtf(fmaxf(cc, 1e-24f));
    }
    __syncthreads();

    // ---- GEMM1: sims (raw dots), 4m x 4p per thread, packed f32x2 ----
    ull a00 = 0, a01 = 0, a10 = 0, a11 = 0, a20 = 0, a21 = 0, a30 = 0, a31 = 0;
    {
        const float* qrow = qt + m0;
        const float* crow = ct + p0;
        #pragma unroll 4
        for (int k = 0; k < DDIM; ++k) {
            float4 qv = *reinterpret_cast<const float4*>(qrow + k * QPITCH);
            ulonglong2 cv = *reinterpret_cast<const ulonglong2*>(crow + k * CPITCH);
            ull q0 = pack2dup(qv.x), q1 = pack2dup(qv.y);
            ull q2 = pack2dup(qv.z), q3 = pack2dup(qv.w);
            ffma2(a00, q0, cv.x); ffma2(a01, q0, cv.y);
            ffma2(a10, q1, cv.x); ffma2(a11, q1, cv.y);
            ffma2(a20, q2, cv.x); ffma2(a21, q2, cv.y);
            ffma2(a30, q3, cv.x); ffma2(a31, q3, cv.y);
        }
    }
    __syncthreads();   // all Qt reads done; wt (alias of qt rows 0..63) may now be written

    // ---- Epilogue: cosine scale + mask -> wt[p][m] (transposed sims) ----
    {
        int4 mk = reinterpret_cast<const int4*>(gmask)[tx];
        const float c0 = cis[p0 + 0], c1 = cis[p0 + 1];
        const float c2 = cis[p0 + 2], c3 = cis[p0 + 3];
        float2 r0, r1;
        float simv[4][4];
        r0 = unpack2(a00); r1 = unpack2(a01);
        simv[0][0] = r0.x; simv[0][1] = r0.y; simv[0][2] = r1.x; simv[0][3] = r1.y;
        r0 = unpack2(a10); r1 = unpack2(a11);
        simv[1][0] = r0.x; simv[1][1] = r0.y; simv[1][2] = r1.x; simv[1][3] = r1.y;
        r0 = unpack2(a20); r1 = unpack2(a21);
        simv[2][0] = r0.x; simv[2][1] = r0.y; simv[2][2] = r1.x; simv[2][3] = r1.y;
        r0 = unpack2(a30); r1 = unpack2(a31);
        simv[3][0] = r0.x; simv[3][1] = r0.y; simv[3][2] = r1.x; simv[3][3] = r1.y;
        #pragma unroll
        for (int i = 0; i < 4; ++i) {
            float qr = qrs[m0 + i];
            wt[(p0 + 0) * QPITCH + m0 + i] = mk.x ? simv[i][0] * qr * c0 : -1e9f;
            wt[(p0 + 1) * QPITCH + m0 + i] = mk.y ? simv[i][1] * qr * c1 : -1e9f;
            wt[(p0 + 2) * QPITCH + m0 + i] = mk.z ? simv[i][2] * qr * c2 : -1e9f;
            wt[(p0 + 3) * QPITCH + m0 + i] = mk.w ? simv[i][3] * qr * c3 : -1e9f;
        }
    }

    // ---- Load Craw (row-major centroids) into the dead Ct region (L2-hot) ----
    #pragma unroll
    for (int i = 0; i < 8; ++i) {
        int idx4 = t + i * NTHREADS;
        reinterpret_cast<float4*>(craw)[idx4] = gc4[idx4];
    }
    __syncthreads();

    // ---- Softmax + argmax: 4 lanes per row (m = t>>2, part = t&3) ----
    {
        const int m = t >> 2, part = t & 3;
        float locv[16];
        float mx = -INFINITY;
        int   mi = PDIM;
        #pragma unroll
        for (int i = 0; i < 16; ++i) {
            int p = part * 16 + i;
            float v = wt[p * QPITCH + m];
            locv[i] = v;
            if (v > mx) { mx = v; mi = p; }
        }
        #pragma unroll
        for (int off = 1; off < 4; off <<= 1) {
            float omx = __shfl_xor_sync(0xffffffffu, mx, off);
            int   omi = __shfl_xor_sync(0xffffffffu, mi, off);
            if (omx > mx || (omx == mx && omi < mi)) { mx = omx; mi = omi; }
        }
        float ssum = 0.f;
        #pragma unroll
        for (int i = 0; i < 16; ++i) {
            float e = expf(locv[i] - mx);
            locv[i] = e;
            ssum += e;
        }
        #pragma unroll
        for (int off = 1; off < 4; off <<= 1)
            ssum += __shfl_xor_sync(0xffffffffu, ssum, off);
        const float inv = 1.0f / ssum;

        float4* gwrow = reinterpret_cast<float4*>(gw + (size_t)(mbase + m) * PDIM + part * 16);
        #pragma unroll
        for (int j = 0; j < 4; ++j) {
            float w0 = locv[4 * j + 0] * inv;
            float w1 = locv[4 * j + 1] * inv;
            float w2 = locv[4 * j + 2] * inv;
            float w3 = locv[4 * j + 3] * inv;
            int p = part * 16 + 4 * j;
            wt[(p + 0) * QPITCH + m] = w0;
            wt[(p + 1) * QPITCH + m] = w1;
            wt[(p + 2) * QPITCH + m] = w2;
            wt[(p + 3) * QPITCH + m] = w3;
            gwrow[j] = make_float4(w0, w1, w2, w3);
        }
        if (part == 0) ghard[mbase + m] = (float)mi;
    }
    __syncthreads();

    // ---- GEMM2: ctx[m][d] = sum_p w[m][p] * C[p][d], packed f32x2 ----
    const float* wrow = wt + m0;
    #pragma unroll
    for (int dbh = 0; dbh < 2; ++dbh) {
        const int d0 = dbh * 128 + tx * 4;
        ull b000=0,b001=0,b010=0,b011=0,b020=0,b021=0,b030=0,b031=0;  // db slice 0
        ull b100=0,b101=0,b110=0,b111=0,b120=0,b121=0,b130=0,b131=0;  // db slice 1 (+64)
        const float* c0p = craw + d0;
        const float* c1p = craw + d0 + 64;
        #pragma unroll 4
        for (int p = 0; p < PDIM; ++p) {
            float4 wv = *reinterpret_cast<const float4*>(wrow + p * QPITCH);
            ull w0 = pack2dup(wv.x), w1 = pack2dup(wv.y);
            ull w2 = pack2dup(wv.z), w3 = pack2dup(wv.w);
            ulonglong2 cva = *reinterpret_cast<const ulonglong2*>(c0p + p * DDIM);
            ffma2(b000, w0, cva.x); ffma2(b001, w0, cva.y);
            ffma2(b010, w1, cva.x); ffma2(b011, w1, cva.y);
            ffma2(b020, w2, cva.x); ffma2(b021, w2, cva.y);
            ffma2(b030, w3, cva.x); ffma2(b031, w3, cva.y);
            ulonglong2 cvb = *reinterpret_cast<const ulonglong2*>(c1p + p * DDIM);
            ffma2(b100, w0, cvb.x); ffma2(b101, w0, cvb.y);
            ffma2(b110, w1, cvb.x); ffma2(b111, w1, cvb.y);
            ffma2(b120, w2, cvb.x); ffma2(b121, w2, cvb.y);
            ffma2(b130, w3, cvb.x); ffma2(b131, w3, cvb.y);
        }
        float* crow0 = gctx + (size_t)(mbase + m0) * DDIM + d0;
        {
            float2 x0, x1;
            x0 = unpack2(b000); x1 = unpack2(b001);
            *reinterpret_cast<float4*>(crow0 + 0 * DDIM) = make_float4(x0.x, x0.y, x1.x, x1.y);
            x0 = unpack2(b010); x1 = unpack2(b011);
            *reinterpret_cast<float4*>(crow0 + 1 * DDIM) = make_float4(x0.x, x0.y, x1.x, x1.y);
            x0 = unpack2(b020); x1 = unpack2(b021);
            *reinterpret_cast<float4*>(crow0 + 2 * DDIM) = make_float4(x0.x, x0.y, x1.x, x1.y);
            x0 = unpack2(b030); x1 = unpack2(b031);
            *reinterpret_cast<float4*>(crow0 + 3 * DDIM) = make_float4(x0.x, x0.y, x1.x, x1.y);
            x0 = unpack2(b100); x1 = unpack2(b101);
            *reinterpret_cast<float4*>(crow0 + 0 * DDIM + 64) = make_float4(x0.x, x0.y, x1.x, x1.y);
            x0 = unpack2(b110); x1 = unpack2(b111);
            *reinterpret_cast<float4*>(crow0 + 1 * DDIM + 64) = make_float4(x0.x, x0.y, x1.x, x1.y);
            x0 = unpack2(b120); x1 = unpack2(b121);
            *reinterpret_cast<float4*>(crow0 + 2 * DDIM + 64) = make_float4(x0.x, x0.y, x1.x, x1.y);
            x0 = unpack2(b130); x1 = unpack2(b131);
            *reinterpret_cast<float4*>(crow0 + 3 * DDIM + 64) = make_float4(x0.x, x0.y, x1.x, x1.y);
        }
    }
}

extern "C" void kernel_launch(void* const* d_in, const int* in_sizes, int n_in,
                              void* d_out, int out_size)
{
    const float* q = (const float*)d_in[0];
    const float* c = (const float*)d_in[1];
    const int*   mask = (const int*)d_in[2];

    const int Pn = in_sizes[2];              // 64
    const int Dn = in_sizes[1] / Pn;         // 256
    const int B  = in_sizes[0] / Dn;         // 131072

    float* out  = (float*)d_out;
    float* ctx  = out;                           // [B, D]
    float* w    = out + (size_t)B * Dn;          // [B, P]
    float* hard = w   + (size_t)B * Pn;          // [B]

    const size_t shmem = SMEM_FLOATS * sizeof(float);   // 208640 B
    cudaFuncSetAttribute(centroid_kernel,
                         cudaFuncAttributeMaxDynamicSharedMemorySize, (int)shmem);
    centroid_kernel<<<B / MTILE, NTHREADS, shmem>>>(q, c, mask, ctx, w, hard);
}

// round 5
// speedup vs baseline: 1.7903x; 1.3542x over previous
#include <cuda_runtime.h>
#include <cuda_bf16.h>
#include <math.h>
#include <stdint.h>

#define DDIM 256
#define PDIM 64
#define MTILE 128
#define NTHREADS 512

// row pitches (bytes); all ≡16 (mod 128) -> conflict-free ldmatrix row sets
#define QP 272    // 136 bf16
#define CP 272
#define SP 272    // sims: 68 f32
#define WP 144    // 72 bf16
#define TP 144

// ---- smem byte offsets ----
// phase A: Q splits [128][136]bf16 x3, C splits [64][136]bf16 x3
#define QH_O 0
#define QM_O 34816
#define QL_O 69632
#define CH_O 104448
#define CM_O 121856
#define CL_O 139264
// phase B/C (alias phase A, dead after GEMM1):
#define SIMS_O 0          // [128][68] f32
#define WH_O 36864        // [128][72] bf16
#define WL_O 55296
#define CTH_O 73728       // [256][72] bf16
#define CTL_O 110592
// scalars
#define QSS_O 156672      // 128 f32
#define CQQ_O 157184      // 64 f32
#define CISM_O 157440     // 64 f32
#define NEGM_O 157696     // 64 f32
#define SMEM_BYTES 157952

__device__ __forceinline__ uint32_t smem_u32(const void* p) {
    uint32_t a;
    asm("{ .reg .u64 t; cvta.to.shared.u64 t, %1; cvt.u32.u64 %0, t; }" : "=r"(a) : "l"(p));
    return a;
}
__device__ __forceinline__ void ldsm4(uint32_t addr, uint32_t& r0, uint32_t& r1,
                                      uint32_t& r2, uint32_t& r3) {
    asm volatile("ldmatrix.sync.aligned.m8n8.x4.shared.b16 {%0,%1,%2,%3}, [%4];"
                 : "=r"(r0), "=r"(r1), "=r"(r2), "=r"(r3) : "r"(addr));
}
__device__ __forceinline__ void mma16816(float* d, uint32_t a0, uint32_t a1, uint32_t a2,
                                         uint32_t a3, uint32_t b0, uint32_t b1) {
    asm volatile("mma.sync.aligned.m16n8k16.row.col.f32.bf16.bf16.f32 "
                 "{%0,%1,%2,%3}, {%4,%5,%6,%7}, {%8,%9}, {%0,%1,%2,%3};"
                 : "+f"(d[0]), "+f"(d[1]), "+f"(d[2]), "+f"(d[3])
                 : "r"(a0), "r"(a1), "r"(a2), "r"(a3), "r"(b0), "r"(b1));
}

// fp32 -> 3 bf16 splits (x - float(hi) exact in fp32)
__device__ __forceinline__ void split3(float x, unsigned short& h, unsigned short& m,
                                       unsigned short& l) {
    __nv_bfloat16 bh = __float2bfloat16(x);
    float r = x - __bfloat162float(bh);
    __nv_bfloat16 bm = __float2bfloat16(r);
    __nv_bfloat16 bl = __float2bfloat16(r - __bfloat162float(bm));
    h = __bfloat16_as_ushort(bh);
    m = __bfloat16_as_ushort(bm);
    l = __bfloat16_as_ushort(bl);
}
__device__ __forceinline__ void split2(float x, unsigned short& h, unsigned short& l) {
    __nv_bfloat16 bh = __float2bfloat16(x);
    __nv_bfloat16 bl = __float2bfloat16(x - __bfloat162float(bh));
    h = __bfloat16_as_ushort(bh);
    l = __bfloat16_as_ushort(bl);
}
__device__ __forceinline__ uint32_t pk(unsigned short a, unsigned short b) {
    return (uint32_t)a | ((uint32_t)b << 16);
}
// 8 fp32 -> 16B in each of 3 split buffers at byte offset off; accumulate sumsq
__device__ __forceinline__ void conv8(const float4* src, char* dh, char* dm, char* dl,
                                      uint32_t off, float& acc) {
    float4 a = src[0], b = src[1];
    float xs[8] = {a.x, a.y, a.z, a.w, b.x, b.y, b.z, b.w};
    unsigned short h[8], m[8], l[8];
    #pragma unroll
    for (int i = 0; i < 8; ++i) {
        acc = fmaf(xs[i], xs[i], acc);
        split3(xs[i], h[i], m[i], l[i]);
    }
    *(uint4*)(dh + off) = make_uint4(pk(h[0], h[1]), pk(h[2], h[3]), pk(h[4], h[5]), pk(h[6], h[7]));
    *(uint4*)(dm + off) = make_uint4(pk(m[0], m[1]), pk(m[2], m[3]), pk(m[4], m[5]), pk(m[6], m[7]));
    *(uint4*)(dl + off) = make_uint4(pk(l[0], l[1]), pk(l[2], l[3]), pk(l[4], l[5]), pk(l[6], l[7]));
}

__global__ void __launch_bounds__(NTHREADS, 1)
centroid_hmma_kernel(const float* __restrict__ gq,
                     const float* __restrict__ gc,
                     const int* __restrict__ gmask,
                     float* __restrict__ gctx,
                     float* __restrict__ gw,
                     float* __restrict__ ghard)
{
    extern __shared__ char sm[];
    const uint32_t smb = smem_u32(sm);
    const int t = threadIdx.x;
    const int wid = t >> 5, lane = t & 31;
    const int mbase = blockIdx.x * MTILE;

    float* qssf = (float*)(sm + QSS_O);
    float* cqqf = (float*)(sm + CQQ_O);
    float* cism = (float*)(sm + CISM_O);
    float* negm = (float*)(sm + NEGM_O);

    const int qrow = t >> 2, qseg = t & 3;   // Q convert: 4 thr/row, 32 k each
    const int crow = t >> 3, cseg = t & 7;   // C convert: 8 thr/row, 16 k each
    const int mrow = (wid & 7) * 16;         // warp M tile
    const int ncol = (wid >> 3) * 32;        // warp N tile (GEMM1)
    const uint32_t lrow = (uint32_t)(lane & 15);
    const uint32_t lkoff = (uint32_t)((lane >> 4) * 16);

    float qacc = 0.f, cacc = 0.f;
    float acc[4][4];
    #pragma unroll
    for (int i = 0; i < 4; ++i)
        #pragma unroll
        for (int j = 0; j < 4; ++j) acc[i][j] = 0.f;

    // =================== GEMM1 over two K-halves ===================
    #pragma unroll 1
    for (int kc = 0; kc < 2; ++kc) {
        // convert Q chunk [128][128]
        {
            const float4* src = (const float4*)(gq + (size_t)(mbase + qrow) * DDIM + kc * 128 + qseg * 32);
            uint32_t base = (uint32_t)(qrow * QP + qseg * 64);
            #pragma unroll
            for (int j = 0; j < 4; ++j)
                conv8(src + 2 * j, sm + QH_O, sm + QM_O, sm + QL_O, base + j * 16, qacc);
        }
        // convert C chunk [64][128]
        {
            const float4* src = (const float4*)(gc + (size_t)crow * DDIM + kc * 128 + cseg * 16);
            uint32_t base = (uint32_t)(crow * CP + cseg * 32);
            #pragma unroll
            for (int j = 0; j < 2; ++j)
                conv8(src + 2 * j, sm + CH_O, sm + CM_O, sm + CL_O, base + j * 16, cacc);
        }
        if (kc == 1) {
            qacc += __shfl_xor_sync(0xffffffffu, qacc, 1);
            qacc += __shfl_xor_sync(0xffffffffu, qacc, 2);
            if ((t & 3) == 0) qssf[qrow] = qacc;
            cacc += __shfl_xor_sync(0xffffffffu, cacc, 1);
            cacc += __shfl_xor_sync(0xffffffffu, cacc, 2);
            cacc += __shfl_xor_sync(0xffffffffu, cacc, 4);
            if ((t & 7) == 0) cqqf[crow] = cacc;
        }
        __syncthreads();
        if (kc == 1 && t < 64) {
            int mk = gmask[t];
            cism[t] = mk ? rsqrtf(fmaxf(cqqf[t], 1e-24f)) : 0.f;
            negm[t] = mk ? 0.f : -1e9f;
        }
        // 6 split passes: hh, hm, mh, hl, lh, mm
        const uint32_t qo[3] = {QH_O, QM_O, QL_O};
        const uint32_t co[3] = {CH_O, CM_O, CL_O};
        const int pq[6] = {0, 0, 1, 0, 2, 1};
        const int pc[6] = {0, 1, 0, 2, 0, 1};
        #pragma unroll 1
        for (int ps = 0; ps < 6; ++ps) {
            uint32_t abase = smb + qo[pq[ps]] + (uint32_t)(mrow + lrow) * QP + lkoff;
            uint32_t bbase = smb + co[pc[ps]] + (uint32_t)(ncol + lrow) * CP + lkoff;
            uint32_t bbase2 = bbase + 16 * CP;
            #pragma unroll
            for (int ks = 0; ks < 8; ++ks) {
                uint32_t a0, a1, a2, a3, e0, e1, e2, e3;
                ldsm4(abase + ks * 32, a0, a1, a2, a3);
                ldsm4(bbase + ks * 32, e0, e1, e2, e3);
                mma16816(acc[0], a0, a1, a2, a3, e0, e2);
                mma16816(acc[1], a0, a1, a2, a3, e1, e3);
                ldsm4(bbase2 + ks * 32, e0, e1, e2, e3);
                mma16816(acc[2], a0, a1, a2, a3, e0, e2);
                mma16816(acc[3], a0, a1, a2, a3, e1, e3);
            }
        }
        __syncthreads();   // operand buffers reusable (next half / phase B aliases)
    }

    // ---- store raw sims to smem [128][68] f32 ----
    {
        int r0 = mrow + (lane >> 2);
        int cb = ncol + (lane & 3) * 2;
        #pragma unroll
        for (int nt = 0; nt < 4; ++nt) {
            *(float2*)(sm + SIMS_O + r0 * SP + (cb + nt * 8) * 4) = make_float2(acc[nt][0], acc[nt][1]);
            *(float2*)(sm + SIMS_O + (r0 + 8) * SP + (cb + nt * 8) * 4) = make_float2(acc[nt][2], acc[nt][3]);
        }
    }
    __syncthreads();

    // =================== softmax/argmax (t<128) || C^T split convert (t>=128) ===================
    if (t < 128) {
        const int m = t;
        const float qr = rsqrtf(fmaxf(qssf[m], 1e-24f));
        const float4* srow = (const float4*)(sm + SIMS_O + m * SP);
        float s[64];
        float mx = -INFINITY;
        int mi = PDIM;
        #pragma unroll
        for (int g = 0; g < 16; ++g) {
            float4 v = srow[g];
            float vv[4] = {v.x, v.y, v.z, v.w};
            #pragma unroll
            for (int i = 0; i < 4; ++i) {
                int p = g * 4 + i;
                float val = fmaf(vv[i] * qr, cism[p], negm[p]);
                s[p] = val;
                if (val > mx) { mx = val; mi = p; }   // strict >: first index wins
            }
        }
        float ssum = 0.f;
        #pragma unroll
        for (int p = 0; p < 64; ++p) {
            float e = expf(s[p] - mx);
            s[p] = e;
            ssum += e;
        }
        const float inv = 1.0f / ssum;
        float4* gwp = (float4*)(gw + (size_t)(mbase + m) * PDIM);
        char* wh = sm + WH_O + m * WP;
        char* wl = sm + WL_O + m * WP;
        #pragma unroll
        for (int g = 0; g < 16; ++g) {
            float w0 = s[4 * g + 0] * inv, w1 = s[4 * g + 1] * inv;
            float w2 = s[4 * g + 2] * inv, w3 = s[4 * g + 3] * inv;
            gwp[g] = make_float4(w0, w1, w2, w3);
            unsigned short h0, l0, h1, l1, h2, l2, h3, l3;
            split2(w0, h0, l0); split2(w1, h1, l1);
            split2(w2, h2, l2); split2(w3, h3, l3);
            *(uint2*)(wh + g * 8) = make_uint2(pk(h0, h1), pk(h2, h3));
            *(uint2*)(wl + g * 8) = make_uint2(pk(l0, l1), pk(l2, l3));
        }
        ghard[mbase + m] = (float)mi;
    } else {
        // C^T splits: [d=256 rows][p=64] bf16, pitch 144B
        for (int idx = t - 128; idx < PDIM * DDIM; idx += 384) {
            int p = idx >> 8, d = idx & 255;
            unsigned short h, l;
            split2(gc[idx], h, l);
            *(unsigned short*)(sm + CTH_O + d * TP + p * 2) = h;
            *(unsigned short*)(sm + CTL_O + d * TP + p * 2) = l;
        }
    }
    __syncthreads();

    // =================== GEMM2: ctx[m][d] = sum_p W[m][p] * C[p][d] ===================
    {
        const int dcol = (wid >> 3) * 128;
        float dd[16][4];
        #pragma unroll
        for (int i = 0; i < 16; ++i)
            #pragma unroll
            for (int j = 0; j < 4; ++j) dd[i][j] = 0.f;

        const uint32_t wo2[3] = {WH_O, WH_O, WL_O};
        const uint32_t to2[3] = {CTH_O, CTL_O, CTH_O};
        #pragma unroll 1
        for (int ps = 0; ps < 3; ++ps) {
            uint32_t abase = smb + wo2[ps] + (uint32_t)(mrow + lrow) * WP + lkoff;
            #pragma unroll
            for (int ks = 0; ks < 4; ++ks) {
                uint32_t a0, a1, a2, a3;
                ldsm4(abase + ks * 32, a0, a1, a2, a3);
                #pragma unroll
                for (int ng = 0; ng < 8; ++ng) {
                    uint32_t e0, e1, e2, e3;
                    uint32_t bb = smb + to2[ps] + (uint32_t)(dcol + ng * 16 + lrow) * TP + ks * 32 + lkoff;
                    ldsm4(bb, e0, e1, e2, e3);
                    mma16816(dd[2 * ng + 0], a0, a1, a2, a3, e0, e2);
                    mma16816(dd[2 * ng + 1], a0, a1, a2, a3, e1, e3);
                }
            }
        }
        // store context
        int r0 = mrow + (lane >> 2);
        float* g0 = gctx + (size_t)(mbase + r0) * DDIM;
        #pragma unroll
        for (int nt = 0; nt < 16; ++nt) {
            int col = dcol + nt * 8 + (lane & 3) * 2;
            *(float2*)(g0 + col) = make_float2(dd[nt][0], dd[nt][1]);
            *(float2*)(g0 + 8 * DDIM + col) = make_float2(dd[nt][2], dd[nt][3]);
        }
    }
}

extern "C" void kernel_launch(void* const* d_in, const int* in_sizes, int n_in,
                              void* d_out, int out_size)
{
    const float* q = (const float*)d_in[0];
    const float* c = (const float*)d_in[1];
    const int*   mask = (const int*)d_in[2];

    const int Pn = in_sizes[2];              // 64
    const int Dn = in_sizes[1] / Pn;         // 256
    const int B  = in_sizes[0] / Dn;         // 131072

    float* out  = (float*)d_out;
    float* ctx  = out;                           // [B, D]
    float* w    = out + (size_t)B * Dn;          // [B, P]
    float* hard = w + (size_t)B * Pn;            // [B]

    cudaFuncSetAttribute(centroid_hmma_kernel,
                         cudaFuncAttributeMaxDynamicSharedMemorySize, SMEM_BYTES);
    centroid_hmma_kernel<<<B / MTILE, NTHREADS, SMEM_BYTES>>>(q, c, mask, ctx, w, hard);
}